// round 10
// baseline (speedup 1.0000x reference)
#include <cuda_runtime.h>

#define TPB 128
#define NF 10
#define EDIM 60
#define NC 64
#define DKDIM 5
#define INV_SQRT5 0.44721359549995793f

typedef unsigned long long u64;

// Packed f32x2 FMA — PTX-only; ptxas never auto-fuses from C++ (sm_100+).
#define FMA2(d, a, b, c) \
    asm("fma.rn.f32x2 %0, %1, %2, %3;" : "=l"(d) : "l"(a), "l"(b), "l"(c))
#define PACK2(d, lo, hi) \
    asm("mov.b64 %0, {%1, %2};" : "=l"(d) : "f"(lo), "f"(hi))

__device__ u64 g_K2[NC * 6];   // K duplicated per-lane pairs (k,k), stride 6 (48B, 16B-aligned)

// ---------------------------------------------------------------------------
__global__ void precompute_K_kernel(const float* __restrict__ Wk,
                                    const float* __restrict__ centroids) {
    int c = threadIdx.x;
    if (c >= NC) return;
    float x0 = centroids[c * 3 + 0];
    float x1 = centroids[c * 3 + 1];
    float x2 = centroids[c * 3 + 2];
    float enc[EDIM];
#pragma unroll
    for (int l = 0; l < NF; l++) {
        float f = (float)(1u << l);
        float s, co;
        sincosf(x0 * f, &s, &co); enc[l * 6 + 0] = s; enc[l * 6 + 3] = co;
        sincosf(x1 * f, &s, &co); enc[l * 6 + 1] = s; enc[l * 6 + 4] = co;
        sincosf(x2 * f, &s, &co); enc[l * 6 + 2] = s; enc[l * 6 + 5] = co;
    }
#pragma unroll
    for (int k = 0; k < 6; k++) {
        float a = 0.f;
        if (k < DKDIM) {
#pragma unroll
            for (int e = 0; e < EDIM; e++) a += enc[e] * Wk[k * EDIM + e];
        }
        u64 p; PACK2(p, a, a);
        g_K2[c * 6 + k] = p;
    }
}

// ---------------------------------------------------------------------------
__device__ __forceinline__ float hsum2(u64 v) {
    return __uint_as_float((unsigned)v) + __uint_as_float((unsigned)(v >> 32));
}

// posenc via double-angle recurrence: 3 sincosf + 2 FMA/dim/level.
// encp layout matches reference flatten: pairs (s0,s1)(s2,c0)(c1,c2) per level.
__device__ __forceinline__ void prep_enc(const float* __restrict__ X, int idx,
                                         u64* encp) {
    float x0 = X[3 * idx + 0];
    float x1 = X[3 * idx + 1];
    float x2 = X[3 * idx + 2];
    float s0, c0, s1, c1, s2, c2;
    sincosf(x0, &s0, &c0);
    sincosf(x1, &s1, &c1);
    sincosf(x2, &s2, &c2);
#pragma unroll
    for (int l = 0; l < NF; l++) {
        PACK2(encp[l * 3 + 0], s0, s1);
        PACK2(encp[l * 3 + 1], s2, c0);
        PACK2(encp[l * 3 + 2], c1, c2);
        if (l < NF - 1) {
            float t, u;
            t = s0 * c0; u = fmaf(c0, c0, -0.5f); s0 = t + t; c0 = u + u;
            t = s1 * c1; u = fmaf(c1, c1, -0.5f); s1 = t + t; c1 = u + u;
            t = s2 * c2; u = fmaf(c2, c2, -0.5f); s2 = t + t; c2 = u + u;
        }
    }
}

// q[k] = (enc . Wq_k) / sqrt(5), all packed math.
__device__ __forceinline__ void compute_q(const u64* encp, const u64* sWqP,
                                          float* q) {
#pragma unroll
    for (int k = 0; k < DKDIM; k++) {
        u64 acc = 0;
        const ulonglong2* wp = (const ulonglong2*)(sWqP + k * 30);
#pragma unroll
        for (int i = 0; i < 15; i++) {
            ulonglong2 w = wp[i];
            FMA2(acc, encp[2 * i],     w.x, acc);
            FMA2(acc, encp[2 * i + 1], w.y, acc);
        }
        q[k] = hsum2(acc) * INV_SQRT5;
    }
}

// kmeans_rgb: 3 LM rows of own cluster, packed.
__device__ __forceinline__ void compute_km(const float* sLM, const u64* encp,
                                           int cc, float* km) {
    const ulonglong2* rp = (const ulonglong2*)(sLM + 3 * cc * EDIM);
    u64 m0 = 0, m1 = 0, m2 = 0;
#pragma unroll
    for (int t = 0; t < 15; t++) {
        ulonglong2 a0 = rp[t], a1 = rp[15 + t], a2 = rp[30 + t];
        u64 e0 = encp[2 * t], e1 = encp[2 * t + 1];
        FMA2(m0, a0.x, e0, m0); FMA2(m0, a0.y, e1, m0);
        FMA2(m1, a1.x, e0, m1); FMA2(m1, a1.y, e1, m1);
        FMA2(m2, a2.x, e0, m2); FMA2(m2, a2.y, e1, m2);
    }
    km[0] = hsum2(m0); km[1] = hsum2(m1); km[2] = hsum2(m2);
}

__device__ __forceinline__ void store_point(
    float* __restrict__ d_out, const float* sWv, int idx, int N, int mode,
    const float* km, const u64* g, float Z)
{
    float invZ = 1.0f / Z;
    float t0 = hsum2(g[0]) * invZ;
    float t1 = hsum2(g[1]) * invZ;
    float t2 = hsum2(g[2]) * invZ;
    float at0 = sWv[0] * t0 + sWv[1] * t1 + sWv[2] * t2;
    float at1 = sWv[3] * t0 + sWv[4] * t1 + sWv[5] * t2;
    float at2 = sWv[6] * t0 + sWv[7] * t1 + sWv[8] * t2;
    const float TR = 1.0f;
    d_out[3 * idx + 0] = km[0] * TR + at0 * (1.0f - TR);
    d_out[3 * idx + 1] = km[1] * TR + at1 * (1.0f - TR);
    d_out[3 * idx + 2] = km[2] * TR + at2 * (1.0f - TR);
    if (mode == 3) {
        float* kmp = d_out + 3 * (size_t)N;
        float* atp = d_out + 6 * (size_t)N;
        kmp[3 * idx + 0] = km[0];
        kmp[3 * idx + 1] = km[1];
        kmp[3 * idx + 2] = km[2];
        atp[3 * idx + 0] = at0;
        atp[3 * idx + 1] = at1;
        atp[3 * idx + 2] = at2;
    }
}

// ---------------------------------------------------------------------------
// Two points per thread, 3 blocks/SM (regs <= 170) for stall coverage.
// Unnormalized softmax (no max pass — scores are O(1)); all math packed f32x2.
// ---------------------------------------------------------------------------
__global__ __launch_bounds__(TPB, 3) void csa_kernel(
    const float* __restrict__ X,
    const int*   __restrict__ cids,
    const float* __restrict__ LM,
    const float* __restrict__ Wq,
    const float* __restrict__ Wv,
    float* __restrict__ d_out,
    int N, int mode)
{
    __shared__ __align__(16) float sLM[192 * EDIM];   // 46080 B
    __shared__ __align__(16) u64 sK2[NC * 6];         //  3072 B
    __shared__ __align__(16) u64 sWqP[DKDIM * 30];    //  1200 B
    __shared__ float sWv[9];

    for (int i = threadIdx.x; i < 192 * EDIM / 4; i += TPB)
        ((float4*)sLM)[i] = ((const float4*)LM)[i];
    for (int i = threadIdx.x; i < NC * 6; i += TPB) sK2[i] = g_K2[i];
    for (int i = threadIdx.x; i < DKDIM * 30; i += TPB)
        sWqP[i] = ((const u64*)Wq)[i];                // Wq rows contiguous, even
    if (threadIdx.x < 9) sWv[threadIdx.x] = Wv[threadIdx.x];
    __syncthreads();

    int base = blockIdx.x * (TPB * 2) + threadIdx.x;
    int iA = base, iB = base + TPB;
    int pA = min(iA, N - 1), pB = min(iB, N - 1);

    u64 encA[EDIM / 2], encB[EDIM / 2];
    prep_enc(X, pA, encA);
    prep_enc(X, pB, encB);

    float qA[DKDIM], qB[DKDIM];
    compute_q(encA, sWqP, qA);
    compute_q(encB, sWqP, qB);
    u64 qp[DKDIM];
#pragma unroll
    for (int k = 0; k < DKDIM; k++) PACK2(qp[k], qA[k], qB[k]);

    float ZA = 0.f, ZB = 0.f;
    u64 gA[3] = {0, 0, 0}, gB[3] = {0, 0, 0};

    for (int c = 0; c < NC; c++) {
        // scores for both points at once: sp = (sA, sB)
        const u64* kc = sK2 + c * 6;
        ulonglong2 k01 = ((const ulonglong2*)kc)[0];
        ulonglong2 k23 = ((const ulonglong2*)kc)[1];
        u64 k4 = kc[4];
        u64 sp = 0;
        FMA2(sp, qp[0], k01.x, sp);
        FMA2(sp, qp[1], k01.y, sp);
        FMA2(sp, qp[2], k23.x, sp);
        FMA2(sp, qp[3], k23.y, sp);
        FMA2(sp, qp[4], k4,    sp);
        float wA = __expf(__uint_as_float((unsigned)sp));
        float wB = __expf(__uint_as_float((unsigned)(sp >> 32)));
        ZA += wA; ZB += wB;
        u64 wpA, wpB;
        PACK2(wpA, wA, wA);
        PACK2(wpB, wB, wB);

        u64 rA0 = 0, rA1 = 0, rA2 = 0, rB0 = 0, rB1 = 0, rB2 = 0;
        const ulonglong2* row = (const ulonglong2*)(sLM + 3 * c * EDIM);
#pragma unroll
        for (int t = 0; t < 15; t++) {
            ulonglong2 a0 = row[t];        // broadcast LDS.128
            ulonglong2 a1 = row[15 + t];
            ulonglong2 a2 = row[30 + t];
            u64 e0 = encA[2 * t], e1 = encA[2 * t + 1];
            FMA2(rA0, a0.x, e0, rA0); FMA2(rA0, a0.y, e1, rA0);
            FMA2(rA1, a1.x, e0, rA1); FMA2(rA1, a1.y, e1, rA1);
            FMA2(rA2, a2.x, e0, rA2); FMA2(rA2, a2.y, e1, rA2);
            e0 = encB[2 * t]; e1 = encB[2 * t + 1];
            FMA2(rB0, a0.x, e0, rB0); FMA2(rB0, a0.y, e1, rB0);
            FMA2(rB1, a1.x, e0, rB1); FMA2(rB1, a1.y, e1, rB1);
            FMA2(rB2, a2.x, e0, rB2); FMA2(rB2, a2.y, e1, rB2);
        }
        FMA2(gA[0], wpA, rA0, gA[0]);
        FMA2(gA[1], wpA, rA1, gA[1]);
        FMA2(gA[2], wpA, rA2, gA[2]);
        FMA2(gB[0], wpB, rB0, gB[0]);
        FMA2(gB[1], wpB, rB1, gB[1]);
        FMA2(gB[2], wpB, rB2, gB[2]);
    }

    float kmA[3], kmB[3];
    compute_km(sLM, encA, cids[pA], kmA);
    compute_km(sLM, encB, cids[pB], kmB);

    if (iA < N) store_point(d_out, sWv, iA, N, mode, kmA, gA, ZA);
    if (iB < N) store_point(d_out, sWv, iB, N, mode, kmB, gB, ZB);
}

extern "C" void kernel_launch(void* const* d_in, const int* in_sizes, int n_in,
                              void* d_out, int out_size) {
    const float* X         = (const float*)d_in[0];
    const int*   cids      = (const int*)  d_in[1];
    const float* LM        = (const float*)d_in[2];
    const float* Wq        = (const float*)d_in[3];
    const float* Wk        = (const float*)d_in[4];
    const float* Wv        = (const float*)d_in[5];
    const float* centroids = (const float*)d_in[6];

    int N = in_sizes[0] / 3;
    int mode = (out_size >= 9 * N) ? 3 : 1;

    precompute_K_kernel<<<1, 64>>>(Wk, centroids);
    int blocks = (N + TPB * 2 - 1) / (TPB * 2);
    csa_kernel<<<blocks, TPB>>>(X, cids, LM, Wq, Wv, (float*)d_out, N, mode);
}

// round 11
// speedup vs baseline: 1.1243x; 1.1243x over previous
#include <cuda_runtime.h>

#define TPB 128
#define NF 10
#define EDIM 60
#define NC 64
#define DKDIM 5
#define INV_SQRT5 0.44721359549995793f

typedef unsigned long long u64;

// Packed f32x2 FMA — PTX-only; ptxas never auto-fuses from C++ (sm_100+).
#define FMA2(d, a, b, c) \
    asm("fma.rn.f32x2 %0, %1, %2, %3;" : "=l"(d) : "l"(a), "l"(b), "l"(c))
#define PACK2(d, lo, hi) \
    asm("mov.b64 %0, {%1, %2;}" : "=l"(d) : "f"(lo), "f"(hi))
#undef PACK2
#define PACK2(d, lo, hi) \
    asm("mov.b64 %0, {%1, %2};" : "=l"(d) : "f"(lo), "f"(hi))

__device__ u64 g_K2[NC * 6];   // K duplicated per-lane pairs (k,k), stride 6

// ---------------------------------------------------------------------------
__global__ void precompute_K_kernel(const float* __restrict__ Wk,
                                    const float* __restrict__ centroids) {
    int c = threadIdx.x;
    if (c >= NC) return;
    float x0 = centroids[c * 3 + 0];
    float x1 = centroids[c * 3 + 1];
    float x2 = centroids[c * 3 + 2];
    float enc[EDIM];
#pragma unroll
    for (int l = 0; l < NF; l++) {
        float f = (float)(1u << l);
        float s, co;
        sincosf(x0 * f, &s, &co); enc[l * 6 + 0] = s; enc[l * 6 + 3] = co;
        sincosf(x1 * f, &s, &co); enc[l * 6 + 1] = s; enc[l * 6 + 4] = co;
        sincosf(x2 * f, &s, &co); enc[l * 6 + 2] = s; enc[l * 6 + 5] = co;
    }
#pragma unroll
    for (int k = 0; k < 6; k++) {
        float a = 0.f;
        if (k < DKDIM) {
#pragma unroll
            for (int e = 0; e < EDIM; e++) a += enc[e] * Wk[k * EDIM + e];
        }
        u64 p; PACK2(p, a, a);
        g_K2[c * 6 + k] = p;
    }
}

// ---------------------------------------------------------------------------
__device__ __forceinline__ float hsum2(u64 v) {
    return __uint_as_float((unsigned)v) + __uint_as_float((unsigned)(v >> 32));
}

// posenc via double-angle recurrence: 3 sincosf + 2 FMA/dim/level.
__device__ __forceinline__ void prep_enc(const float* __restrict__ X, int idx,
                                         u64* encp) {
    float x0 = X[3 * idx + 0];
    float x1 = X[3 * idx + 1];
    float x2 = X[3 * idx + 2];
    float s0, c0, s1, c1, s2, c2;
    sincosf(x0, &s0, &c0);
    sincosf(x1, &s1, &c1);
    sincosf(x2, &s2, &c2);
#pragma unroll
    for (int l = 0; l < NF; l++) {
        PACK2(encp[l * 3 + 0], s0, s1);
        PACK2(encp[l * 3 + 1], s2, c0);
        PACK2(encp[l * 3 + 2], c1, c2);
        if (l < NF - 1) {
            float t, u;
            t = s0 * c0; u = fmaf(c0, c0, -0.5f); s0 = t + t; c0 = u + u;
            t = s1 * c1; u = fmaf(c1, c1, -0.5f); s1 = t + t; c1 = u + u;
            t = s2 * c2; u = fmaf(c2, c2, -0.5f); s2 = t + t; c2 = u + u;
        }
    }
}

__device__ __forceinline__ void compute_q(const u64* encp, const u64* sWqP,
                                          float* q) {
#pragma unroll
    for (int k = 0; k < DKDIM; k++) {
        u64 acc = 0;
        const ulonglong2* wp = (const ulonglong2*)(sWqP + k * 30);
#pragma unroll
        for (int i = 0; i < 15; i++) {
            ulonglong2 w = wp[i];
            FMA2(acc, encp[2 * i],     w.x, acc);
            FMA2(acc, encp[2 * i + 1], w.y, acc);
        }
        q[k] = hsum2(acc) * INV_SQRT5;
    }
}

__device__ __forceinline__ void compute_km(const float* sLM, const u64* encp,
                                           int cc, float* km) {
    const ulonglong2* rp = (const ulonglong2*)(sLM + 3 * cc * EDIM);
    u64 m0 = 0, m1 = 0, m2 = 0;
#pragma unroll
    for (int t = 0; t < 15; t++) {
        ulonglong2 a0 = rp[t], a1 = rp[15 + t], a2 = rp[30 + t];
        u64 e0 = encp[2 * t], e1 = encp[2 * t + 1];
        FMA2(m0, a0.x, e0, m0); FMA2(m0, a0.y, e1, m0);
        FMA2(m1, a1.x, e0, m1); FMA2(m1, a1.y, e1, m1);
        FMA2(m2, a2.x, e0, m2); FMA2(m2, a2.y, e1, m2);
    }
    km[0] = hsum2(m0); km[1] = hsum2(m1); km[2] = hsum2(m2);
}

__device__ __forceinline__ void store_point(
    float* __restrict__ d_out, const float* sWv, int idx, int N, int mode,
    const float* km, float t0, float t1, float t2)
{
    float at0 = sWv[0] * t0 + sWv[1] * t1 + sWv[2] * t2;
    float at1 = sWv[3] * t0 + sWv[4] * t1 + sWv[5] * t2;
    float at2 = sWv[6] * t0 + sWv[7] * t1 + sWv[8] * t2;
    const float TR = 1.0f;
    d_out[3 * idx + 0] = km[0] * TR + at0 * (1.0f - TR);
    d_out[3 * idx + 1] = km[1] * TR + at1 * (1.0f - TR);
    d_out[3 * idx + 2] = km[2] * TR + at2 * (1.0f - TR);
    if (mode == 3) {
        float* kmp = d_out + 3 * (size_t)N;
        float* atp = d_out + 6 * (size_t)N;
        kmp[3 * idx + 0] = km[0];
        kmp[3 * idx + 1] = km[1];
        kmp[3 * idx + 2] = km[2];
        atp[3 * idx + 0] = at0;
        atp[3 * idx + 1] = at1;
        atp[3 * idx + 2] = at2;
    }
}

// ---------------------------------------------------------------------------
// Two points per thread, 2 blocks/SM (full 255-reg budget so the scheduler
// and the explicit depth-1 prefetch rotation can hide LDS latency).
// 12 fully-independent packed-FMA accumulator chains; unnormalized softmax.
// ---------------------------------------------------------------------------
__global__ __launch_bounds__(TPB, 2) void csa_kernel(
    const float* __restrict__ X,
    const int*   __restrict__ cids,
    const float* __restrict__ LM,
    const float* __restrict__ Wq,
    const float* __restrict__ Wv,
    float* __restrict__ d_out,
    int N, int mode)
{
    __shared__ __align__(16) float sLM[192 * EDIM + 128];  // +512B overread pad
    __shared__ __align__(16) u64 sK2[NC * 6];
    __shared__ __align__(16) u64 sWqP[DKDIM * 30];
    __shared__ float sWv[9];

    for (int i = threadIdx.x; i < 192 * EDIM / 4; i += TPB)
        ((float4*)sLM)[i] = ((const float4*)LM)[i];
    for (int i = threadIdx.x; i < NC * 6; i += TPB) sK2[i] = g_K2[i];
    for (int i = threadIdx.x; i < DKDIM * 30; i += TPB)
        sWqP[i] = ((const u64*)Wq)[i];
    if (threadIdx.x < 9) sWv[threadIdx.x] = Wv[threadIdx.x];
    __syncthreads();

    int base = blockIdx.x * (TPB * 2) + threadIdx.x;
    int iA = base, iB = base + TPB;
    int pA = min(iA, N - 1), pB = min(iB, N - 1);

    u64 encA[EDIM / 2], encB[EDIM / 2];
    prep_enc(X, pA, encA);
    prep_enc(X, pB, encB);

    float qA[DKDIM], qB[DKDIM];
    compute_q(encA, sWqP, qA);
    compute_q(encB, sWqP, qB);
    u64 qp[DKDIM];
#pragma unroll
    for (int k = 0; k < DKDIM; k++) PACK2(qp[k], qA[k], qB[k]);

    float ZA = 0.f, ZB = 0.f;
    u64 gA0 = 0, gA1 = 0, gA2 = 0, gA3 = 0, gA4 = 0, gA5 = 0;
    u64 gB0 = 0, gB1 = 0, gB2 = 0, gB3 = 0, gB4 = 0, gB5 = 0;

    const ulonglong2* rowc = (const ulonglong2*)sLM;   // 45 ull2 per cluster
    ulonglong2 p0 = rowc[0], p1 = rowc[15], p2 = rowc[30];

    for (int c = 0; c < NC; c++) {
        // packed scores for both points: sp = (sA, sB)
        const u64* kc = sK2 + c * 6;
        ulonglong2 k01 = ((const ulonglong2*)kc)[0];
        ulonglong2 k23 = ((const ulonglong2*)kc)[1];
        u64 k4 = kc[4];
        u64 sp = 0;
        FMA2(sp, qp[0], k01.x, sp);
        FMA2(sp, qp[1], k01.y, sp);
        FMA2(sp, qp[2], k23.x, sp);
        FMA2(sp, qp[3], k23.y, sp);
        FMA2(sp, qp[4], k4,    sp);
        float wA = __expf(__uint_as_float((unsigned)sp));
        float wB = __expf(__uint_as_float((unsigned)(sp >> 32)));
        ZA += wA; ZB += wB;
        u64 wpA, wpB;
        PACK2(wpA, wA, wA);
        PACK2(wpB, wB, wB);

        u64 rA0 = 0, rA1 = 0, rA2 = 0, rA3 = 0, rA4 = 0, rA5 = 0;
        u64 rB0 = 0, rB1 = 0, rB2 = 0, rB3 = 0, rB4 = 0, rB5 = 0;
#pragma unroll
        for (int t = 0; t < 15; t++) {
            // depth-1 prefetch: t+1 within cluster, or cluster c+1's t=0
            int o = (t == 14) ? 45 : (t + 1);
            ulonglong2 n0 = rowc[o];            // broadcast LDS.128
            ulonglong2 n1 = rowc[o + 15];
            ulonglong2 n2 = rowc[o + 30];

            u64 e0 = encA[2 * t], e1 = encA[2 * t + 1];
            FMA2(rA0, p0.x, e0, rA0); FMA2(rA1, p0.y, e1, rA1);
            FMA2(rA2, p1.x, e0, rA2); FMA2(rA3, p1.y, e1, rA3);
            FMA2(rA4, p2.x, e0, rA4); FMA2(rA5, p2.y, e1, rA5);
            e0 = encB[2 * t]; e1 = encB[2 * t + 1];
            FMA2(rB0, p0.x, e0, rB0); FMA2(rB1, p0.y, e1, rB1);
            FMA2(rB2, p1.x, e0, rB2); FMA2(rB3, p1.y, e1, rB3);
            FMA2(rB4, p2.x, e0, rB4); FMA2(rB5, p2.y, e1, rB5);

            p0 = n0; p1 = n1; p2 = n2;
        }
        rowc += 45;

        FMA2(gA0, wpA, rA0, gA0); FMA2(gA1, wpA, rA1, gA1);
        FMA2(gA2, wpA, rA2, gA2); FMA2(gA3, wpA, rA3, gA3);
        FMA2(gA4, wpA, rA4, gA4); FMA2(gA5, wpA, rA5, gA5);
        FMA2(gB0, wpB, rB0, gB0); FMA2(gB1, wpB, rB1, gB1);
        FMA2(gB2, wpB, rB2, gB2); FMA2(gB3, wpB, rB3, gB3);
        FMA2(gB4, wpB, rB4, gB4); FMA2(gB5, wpB, rB5, gB5);
    }

    float invZA = 1.0f / ZA, invZB = 1.0f / ZB;
    float tA0 = (hsum2(gA0) + hsum2(gA1)) * invZA;
    float tA1 = (hsum2(gA2) + hsum2(gA3)) * invZA;
    float tA2 = (hsum2(gA4) + hsum2(gA5)) * invZA;
    float tB0 = (hsum2(gB0) + hsum2(gB1)) * invZB;
    float tB1 = (hsum2(gB2) + hsum2(gB3)) * invZB;
    float tB2 = (hsum2(gB4) + hsum2(gB5)) * invZB;

    float kmA[3], kmB[3];
    compute_km(sLM, encA, cids[pA], kmA);
    compute_km(sLM, encB, cids[pB], kmB);

    if (iA < N) store_point(d_out, sWv, iA, N, mode, kmA, tA0, tA1, tA2);
    if (iB < N) store_point(d_out, sWv, iB, N, mode, kmB, tB0, tB1, tB2);
}

extern "C" void kernel_launch(void* const* d_in, const int* in_sizes, int n_in,
                              void* d_out, int out_size) {
    const float* X         = (const float*)d_in[0];
    const int*   cids      = (const int*)  d_in[1];
    const float* LM        = (const float*)d_in[2];
    const float* Wq        = (const float*)d_in[3];
    const float* Wk        = (const float*)d_in[4];
    const float* Wv        = (const float*)d_in[5];
    const float* centroids = (const float*)d_in[6];

    int N = in_sizes[0] / 3;
    int mode = (out_size >= 9 * N) ? 3 : 1;

    precompute_K_kernel<<<1, 64>>>(Wk, centroids);
    int blocks = (N + TPB * 2 - 1) / (TPB * 2);
    csa_kernel<<<blocks, TPB>>>(X, cids, LM, Wq, Wv, (float*)d_out, N, mode);
}